// round 5
// baseline (speedup 1.0000x reference)
#include <cuda_runtime.h>

#define TPB 256
#define EPB (TPB * 4)          // 1024 edges per block
#define RSTRIDE 13             // 9 (M 3x3) + 3 (beta) + 1 pad; gcd(13,32)=1 -> conflict-free LDS

__device__ __forceinline__ void sparsemax3(float a, float b, float c,
                                           float& o0, float& o1, float& o2) {
    // sort descending via min/max network
    float hi = fmaxf(a, b), lo = fminf(a, b);
    float z1 = fmaxf(hi, c);
    float z3 = fminf(lo, c);
    float z2 = (a + b + c) - z1 - z3;
    // support conditions (k=1 always in support; support set is a prefix)
    bool k2 = (1.0f + 2.0f * z2) > (z1 + z2);
    bool k3 = (1.0f + 3.0f * z3) > (z1 + z2 + z3);
    float ksup, cs;
    if (k3)      { ksup = 3.0f; cs = z1 + z2 + z3; }
    else if (k2) { ksup = 2.0f; cs = z1 + z2; }
    else         { ksup = 1.0f; cs = z1; }
    float tau = (cs - 1.0f) / ksup;
    o0 = fmaxf(a - tau, 0.0f);
    o1 = fmaxf(b - tau, 0.0f);
    o2 = fmaxf(c - tau, 0.0f);
}

__device__ __forceinline__ void edge_compute(
    float p0, float p1, float p2,
    float c0, float c1, float c2,
    int rel, float zeps, float sf,
    const float* __restrict__ sR,
    float& o0, float& o1, float& o2)
{
    const float* r = sR + rel * RSTRIDE;
    // relation-gated bmm: g_i = sum_j M[rel][i][j] * child[j]
    float g0 = fmaf(r[0], c0, fmaf(r[1], c1, r[2] * c2));
    float g1 = fmaf(r[3], c0, fmaf(r[4], c1, r[5] * c2));
    float g2 = fmaf(r[6], c0, fmaf(r[7], c1, r[8] * c2));

    float cc0, cc1, cc2, pp0, pp1, pp2;
    sparsemax3(g0, g1, g2, cc0, cc1, cc2);   // 2nd sparsemax in ref is an exact no-op (idempotent projection)
    sparsemax3(p0, p1, p2, pp0, pp1, pp2);

    float b0 = r[9], b1 = r[10], b2 = r[11];
    float a0 = (1.0f - b0) * pp0 + b0 * cc0;
    float a1 = (1.0f - b1) * pp1 + b1 * cc1;
    float a2 = (1.0f - b2) * pp2 + b2 * cc2;

    // scale(): entropy of clamped+normalized mixture, plus cosine similarity
    float z0 = fmaxf(pp0 + cc0, zeps);
    float z1 = fmaxf(pp1 + cc1, zeps);
    float z2 = fmaxf(pp2 + cc2, zeps);
    float inv = 1.0f / (z0 + z1 + z2);
    z0 *= inv; z1 *= inv; z2 *= inv;
    float ent = -(z0 * __logf(z0) + z1 * __logf(z1) + z2 * __logf(z2));

    float dotpc = pp0 * cc0 + pp1 * cc1 + pp2 * cc2;
    float np = sqrtf(pp0 * pp0 + pp1 * pp1 + pp2 * pp2);
    float nc = sqrtf(cc0 * cc0 + cc1 * cc1 + cc2 * cc2);
    float cosv = 0.1f + dotpc / fmaxf(np * nc, 1e-10f);
    float scale = sf * cosv / ent;

    o0 = fmaxf(a0 * scale, 0.001f);
    o1 = fmaxf(a1 * scale, 0.001f);
    o2 = fmaxf(a2 * scale, 0.001f);
}

__global__ void __launch_bounds__(TPB)
alpha_kernel(const float* __restrict__ prnt,
             const float* __restrict__ child,
             const float* __restrict__ Mg,
             const float* __restrict__ Bg,
             const float* __restrict__ zeps_p,
             const float* __restrict__ sf_p,
             const int*   __restrict__ rels,
             float* __restrict__ out,
             int n)
{
    __shared__ float sR[64 * RSTRIDE];
    __shared__ float sP[EPB * 3];        // prnt tile; reused as out tile
    __shared__ float sC[EPB * 3];        // child tile

    const int tid = threadIdx.x;
    const int base = blockIdx.x * EPB;   // first edge of this block

    const bool full = (base + EPB) <= n;
    const int rem   = n - base;          // edges this block covers (>=1)
    const int nf    = (full ? EPB : rem) * 3;

    // hoisted loads: rels int4 + scalars issue alongside tile staging (one
    // DRAM window instead of two serialized ones)
    int r0, r1, r2, r3;
    if (full) {
        int4 rr = ((const int4*)rels)[(size_t)base / 4 + tid];
        r0 = rr.x; r1 = rr.y; r2 = rr.z; r3 = rr.w;
    } else {
        int e = base + tid * 4;
        r0 = (e + 0 < n) ? rels[e + 0] : 0;
        r1 = (e + 1 < n) ? rels[e + 1] : 0;
        r2 = (e + 2 < n) ? rels[e + 2] : 0;
        r3 = (e + 3 < n) ? rels[e + 3] : 0;
    }
    const float zeps = __ldg(zeps_p);
    const float sf   = __ldg(sf_p);

    // relation table -> shared (M 3x3 row-major + beta, stride 13)
    for (int i = tid; i < 64 * RSTRIDE; i += TPB) {
        int r = i / RSTRIDE, k = i - r * RSTRIDE;
        float v = 0.0f;
        if (k < 9)       v = Mg[r * 9 + k];
        else if (k < 12) v = Bg[r * 3 + (k - 9)];
        sR[i] = v;
    }

    // stage prnt/child tiles: block-contiguous float4 loads (fully coalesced)
    if (full) {
        const float4* gp = (const float4*)prnt + (size_t)base * 3 / 4;
        const float4* gc = (const float4*)child + (size_t)base * 3 / 4;
        float4* sP4 = (float4*)sP;
        float4* sC4 = (float4*)sC;
        #pragma unroll
        for (int j = 0; j < 3; j++) {
            sP4[tid + TPB * j] = gp[tid + TPB * j];
            sC4[tid + TPB * j] = gc[tid + TPB * j];
        }
    } else {
        for (int i = tid; i < EPB * 3; i += TPB) {
            sP[i] = (i < nf) ? prnt[(size_t)base * 3 + i] : 0.25f;
            sC[i] = (i < nf) ? child[(size_t)base * 3 + i] : 0.25f;
        }
    }
    __syncthreads();

    // compute 4 edges/thread from smem (float4 LDS, bank-conflict-free:
    // lane bank offsets 12*l mod 32 tile all banks per 8-lane phase)
    {
        float4* sP4 = (float4*)sP;
        float4* sC4 = (float4*)sC;
        float4 pa = sP4[3 * tid], pb = sP4[3 * tid + 1], pc = sP4[3 * tid + 2];
        float4 ca = sC4[3 * tid], cb = sC4[3 * tid + 1], cc = sC4[3 * tid + 2];

        float4 oa, ob, oc;
        edge_compute(pa.x, pa.y, pa.z,  ca.x, ca.y, ca.z,  r0, zeps, sf, sR, oa.x, oa.y, oa.z);
        edge_compute(pa.w, pb.x, pb.y,  ca.w, cb.x, cb.y,  r1, zeps, sf, sR, oa.w, ob.x, ob.y);
        edge_compute(pb.z, pb.w, pc.x,  cb.z, cb.w, cc.x,  r2, zeps, sf, sR, ob.z, ob.w, oc.x);
        edge_compute(pc.y, pc.z, pc.w,  cc.y, cc.z, cc.w,  r3, zeps, sf, sR, oc.y, oc.z, oc.w);

        // overwrite own region of the prnt tile with results (no cross-thread hazard)
        sP4[3 * tid] = oa; sP4[3 * tid + 1] = ob; sP4[3 * tid + 2] = oc;
    }
    __syncthreads();

    // write out tile: block-contiguous float4 stores (fully coalesced)
    if (full) {
        float4* go = (float4*)out + (size_t)base * 3 / 4;
        const float4* sP4 = (const float4*)sP;
        #pragma unroll
        for (int j = 0; j < 3; j++)
            go[tid + TPB * j] = sP4[tid + TPB * j];
    } else {
        for (int i = tid; i < nf; i += TPB)
            out[(size_t)base * 3 + i] = sP[i];
    }
}

extern "C" void kernel_launch(void* const* d_in, const int* in_sizes, int n_in,
                              void* d_out, int out_size) {
    // metadata order: prnt_probs, child_probs, M, beta, z_epsilon, scale_factor, rels, var_sfx
    const float* prnt  = (const float*)d_in[0];
    const float* child = (const float*)d_in[1];
    const float* Mg    = (const float*)d_in[2];
    const float* Bg    = (const float*)d_in[3];
    const float* zeps  = (const float*)d_in[4];
    const float* sf    = (const float*)d_in[5];
    const int*   rels  = (const int*)d_in[6];
    float* out = (float*)d_out;

    int n = in_sizes[6];                       // number of edges
    int blocks = (n + EPB - 1) / EPB;
    if (blocks == 0) blocks = 1;

    alpha_kernel<<<blocks, TPB>>>(prnt, child, Mg, Bg, zeps, sf, rels, out, n);
}

// round 6
// speedup vs baseline: 1.1119x; 1.1119x over previous
#include <cuda_runtime.h>

#define TPB 256
#define EPB (TPB * 4)          // 1024 edges per block

__device__ __forceinline__ void sparsemax3(float a, float b, float c,
                                           float& o0, float& o1, float& o2) {
    // sort descending via min/max network
    float hi = fmaxf(a, b), lo = fminf(a, b);
    float z1 = fmaxf(hi, c);
    float z3 = fminf(lo, c);
    float z2 = (a + b + c) - z1 - z3;
    // support conditions (k=1 always in support; support set is a prefix)
    bool k2 = (1.0f + 2.0f * z2) > (z1 + z2);
    bool k3 = (1.0f + 3.0f * z3) > (z1 + z2 + z3);
    float ksup, cs;
    if (k3)      { ksup = 3.0f; cs = z1 + z2 + z3; }
    else if (k2) { ksup = 2.0f; cs = z1 + z2; }
    else         { ksup = 1.0f; cs = z1; }
    float tau = (cs - 1.0f) / ksup;
    o0 = fmaxf(a - tau, 0.0f);
    o1 = fmaxf(b - tau, 0.0f);
    o2 = fmaxf(c - tau, 0.0f);
}

// rel table entry: q[i] = (M[i][0], M[i][1], M[i][2], beta[i]), i = 0..2
__device__ __forceinline__ void edge_compute(
    float p0, float p1, float p2,
    float c0, float c1, float c2,
    int rel, float zeps, float sf,
    const float4* __restrict__ sRv,
    float& o0, float& o1, float& o2)
{
    float4 q0 = sRv[rel * 3 + 0];
    float4 q1 = sRv[rel * 3 + 1];
    float4 q2 = sRv[rel * 3 + 2];

    // relation-gated bmm: g_i = dot(M[rel][i][:], child)
    float g0 = fmaf(q0.x, c0, fmaf(q0.y, c1, q0.z * c2));
    float g1 = fmaf(q1.x, c0, fmaf(q1.y, c1, q1.z * c2));
    float g2 = fmaf(q2.x, c0, fmaf(q2.y, c1, q2.z * c2));

    float cc0, cc1, cc2, pp0, pp1, pp2;
    sparsemax3(g0, g1, g2, cc0, cc1, cc2);   // 2nd sparsemax in ref is an exact no-op (idempotent projection)
    sparsemax3(p0, p1, p2, pp0, pp1, pp2);

    float b0 = q0.w, b1 = q1.w, b2 = q2.w;
    float a0 = (1.0f - b0) * pp0 + b0 * cc0;
    float a1 = (1.0f - b1) * pp1 + b1 * cc1;
    float a2 = (1.0f - b2) * pp2 + b2 * cc2;

    // scale(): entropy of clamped+normalized mixture, plus cosine similarity
    float z0 = fmaxf(pp0 + cc0, zeps);
    float z1 = fmaxf(pp1 + cc1, zeps);
    float z2 = fmaxf(pp2 + cc2, zeps);
    float inv = 1.0f / (z0 + z1 + z2);
    z0 *= inv; z1 *= inv; z2 *= inv;
    float ent = -(z0 * __logf(z0) + z1 * __logf(z1) + z2 * __logf(z2));

    float dotpc = pp0 * cc0 + pp1 * cc1 + pp2 * cc2;
    float np = sqrtf(pp0 * pp0 + pp1 * pp1 + pp2 * pp2);
    float nc = sqrtf(cc0 * cc0 + cc1 * cc1 + cc2 * cc2);
    float cosv = 0.1f + dotpc / fmaxf(np * nc, 1e-10f);
    float scale = sf * cosv / ent;

    o0 = fmaxf(a0 * scale, 0.001f);
    o1 = fmaxf(a1 * scale, 0.001f);
    o2 = fmaxf(a2 * scale, 0.001f);
}

__global__ void __launch_bounds__(TPB)
alpha_kernel(const float* __restrict__ prnt,
             const float* __restrict__ child,
             const float* __restrict__ Mg,
             const float* __restrict__ Bg,
             const float* __restrict__ zeps_p,
             const float* __restrict__ sf_p,
             const int*   __restrict__ rels,
             float* __restrict__ out,
             int n)
{
    __shared__ float4 sRv[64 * 3];       // (Mrow0..2 | beta_i) per relation, 48B stride
    __shared__ float sP[EPB * 3];        // prnt tile
    __shared__ float sC[EPB * 3];        // child tile

    const int tid = threadIdx.x;
    const int base = blockIdx.x * EPB;   // first edge of this block

    const bool full = (base + EPB) <= n;
    const int rem   = n - base;
    const int nf    = (full ? EPB : rem) * 3;

    // hoisted: rels + scalars issue alongside tile staging (single DRAM window)
    int r0, r1, r2, r3;
    if (full) {
        int4 rr = ((const int4*)rels)[(size_t)base / 4 + tid];
        r0 = rr.x; r1 = rr.y; r2 = rr.z; r3 = rr.w;
    } else {
        int e = base + tid * 4;
        r0 = (e + 0 < n) ? rels[e + 0] : 0;
        r1 = (e + 1 < n) ? rels[e + 1] : 0;
        r2 = (e + 2 < n) ? rels[e + 2] : 0;
        r3 = (e + 3 < n) ? rels[e + 3] : 0;
    }
    const float zeps = __ldg(zeps_p);
    const float sf   = __ldg(sf_p);

    // relation table -> shared, packed: sRv[rel*3+i] = (M[i][0..2], beta[i])
    if (tid < 64 * 3) {
        int rel = tid / 3, row = tid - rel * 3;
        float4 q;
        q.x = Mg[rel * 9 + row * 3 + 0];
        q.y = Mg[rel * 9 + row * 3 + 1];
        q.z = Mg[rel * 9 + row * 3 + 2];
        q.w = Bg[rel * 3 + row];
        sRv[tid] = q;
    }

    // stage prnt/child tiles: block-contiguous float4 loads (fully coalesced)
    if (full) {
        const float4* gp = (const float4*)prnt + (size_t)base * 3 / 4;
        const float4* gc = (const float4*)child + (size_t)base * 3 / 4;
        float4* sP4 = (float4*)sP;
        float4* sC4 = (float4*)sC;
        #pragma unroll
        for (int j = 0; j < 3; j++) {
            sP4[tid + TPB * j] = gp[tid + TPB * j];
            sC4[tid + TPB * j] = gc[tid + TPB * j];
        }
    } else {
        for (int i = tid; i < EPB * 3; i += TPB) {
            sP[i] = (i < nf) ? prnt[(size_t)base * 3 + i] : 0.25f;
            sC[i] = (i < nf) ? child[(size_t)base * 3 + i] : 0.25f;
        }
    }
    __syncthreads();

    // compute 4 edges/thread from smem (float4 LDS, bank-conflict-free:
    // lane bank offsets 12*l mod 32 tile all banks per 8-lane phase)
    float4* sP4 = (float4*)sP;
    float4* sC4 = (float4*)sC;
    float4 pa = sP4[3 * tid], pb = sP4[3 * tid + 1], pc = sP4[3 * tid + 2];
    float4 ca = sC4[3 * tid], cb = sC4[3 * tid + 1], cc = sC4[3 * tid + 2];

    float4 oa, ob, oc;
    edge_compute(pa.x, pa.y, pa.z,  ca.x, ca.y, ca.z,  r0, zeps, sf, sRv, oa.x, oa.y, oa.z);
    edge_compute(pa.w, pb.x, pb.y,  ca.w, cb.x, cb.y,  r1, zeps, sf, sRv, oa.w, ob.x, ob.y);
    edge_compute(pb.z, pb.w, pc.x,  cb.z, cb.w, cc.x,  r2, zeps, sf, sRv, ob.z, ob.w, oc.x);
    edge_compute(pc.y, pc.z, pc.w,  cc.y, cc.z, cc.w,  r3, zeps, sf, sRv, oc.y, oc.z, oc.w);

    // direct strided float4 stores (no smem round-trip, no second barrier)
    if (full) {
        float4* go = (float4*)out + (size_t)base * 3 / 4;
        go[3 * tid + 0] = oa;
        go[3 * tid + 1] = ob;
        go[3 * tid + 2] = oc;
    } else {
        int e = base + tid * 4;          // this thread's first edge
        float res[12] = {oa.x, oa.y, oa.z, oa.w, ob.x, ob.y, ob.z, ob.w,
                         oc.x, oc.y, oc.z, oc.w};
        int cnt = n - e;                 // edges this thread owns (may be <=0)
        cnt = cnt < 0 ? 0 : (cnt > 4 ? 4 : cnt);
        for (int i = 0; i < cnt * 3; i++)
            out[(size_t)e * 3 + i] = res[i];
    }
}

extern "C" void kernel_launch(void* const* d_in, const int* in_sizes, int n_in,
                              void* d_out, int out_size) {
    // metadata order: prnt_probs, child_probs, M, beta, z_epsilon, scale_factor, rels, var_sfx
    const float* prnt  = (const float*)d_in[0];
    const float* child = (const float*)d_in[1];
    const float* Mg    = (const float*)d_in[2];
    const float* Bg    = (const float*)d_in[3];
    const float* zeps  = (const float*)d_in[4];
    const float* sf    = (const float*)d_in[5];
    const int*   rels  = (const int*)d_in[6];
    float* out = (float*)d_out;

    int n = in_sizes[6];                       // number of edges
    int blocks = (n + EPB - 1) / EPB;
    if (blocks == 0) blocks = 1;

    alpha_kernel<<<blocks, TPB>>>(prnt, child, Mg, Bg, zeps, sf, rels, out, n);
}

// round 11
// speedup vs baseline: 1.2821x; 1.1531x over previous
#include <cuda_runtime.h>

#define TPB 256
#define EPB (TPB * 4)          // 1024 edges per block

__device__ __forceinline__ void sparsemax3(float a, float b, float c,
                                           float& o0, float& o1, float& o2) {
    // sort descending via min/max network
    float hi = fmaxf(a, b), lo = fminf(a, b);
    float z1 = fmaxf(hi, c);
    float z3 = fminf(lo, c);
    float z2 = (a + b + c) - z1 - z3;
    // support conditions (k=1 always in support; support set is a prefix)
    bool k2 = (1.0f + 2.0f * z2) > (z1 + z2);
    bool k3 = (1.0f + 3.0f * z3) > (z1 + z2 + z3);
    float ksup, cs;
    if (k3)      { ksup = 3.0f; cs = z1 + z2 + z3; }
    else if (k2) { ksup = 2.0f; cs = z1 + z2; }
    else         { ksup = 1.0f; cs = z1; }
    float tau = (cs - 1.0f) / ksup;
    o0 = fmaxf(a - tau, 0.0f);
    o1 = fmaxf(b - tau, 0.0f);
    o2 = fmaxf(c - tau, 0.0f);
}

// rel table entry: q[i] = (M[i][0], M[i][1], M[i][2], beta[i]), i = 0..2
__device__ __forceinline__ void edge_compute(
    float p0, float p1, float p2,
    float c0, float c1, float c2,
    int rel, float zeps, float sf,
    const float4* __restrict__ sRv,
    float& o0, float& o1, float& o2)
{
    float4 q0 = sRv[rel * 3 + 0];
    float4 q1 = sRv[rel * 3 + 1];
    float4 q2 = sRv[rel * 3 + 2];

    // relation-gated bmm: g_i = dot(M[rel][i][:], child)
    float g0 = fmaf(q0.x, c0, fmaf(q0.y, c1, q0.z * c2));
    float g1 = fmaf(q1.x, c0, fmaf(q1.y, c1, q1.z * c2));
    float g2 = fmaf(q2.x, c0, fmaf(q2.y, c1, q2.z * c2));

    float cc0, cc1, cc2, pp0, pp1, pp2;
    sparsemax3(g0, g1, g2, cc0, cc1, cc2);   // 2nd sparsemax in ref is an exact no-op (idempotent projection)
    sparsemax3(p0, p1, p2, pp0, pp1, pp2);

    float b0 = q0.w, b1 = q1.w, b2 = q2.w;
    float a0 = (1.0f - b0) * pp0 + b0 * cc0;
    float a1 = (1.0f - b1) * pp1 + b1 * cc1;
    float a2 = (1.0f - b2) * pp2 + b2 * cc2;

    // scale(): entropy of clamped+normalized mixture, plus cosine similarity
    float z0 = fmaxf(pp0 + cc0, zeps);
    float z1 = fmaxf(pp1 + cc1, zeps);
    float z2 = fmaxf(pp2 + cc2, zeps);
    float inv = 1.0f / (z0 + z1 + z2);
    z0 *= inv; z1 *= inv; z2 *= inv;
    float ent = -(z0 * __logf(z0) + z1 * __logf(z1) + z2 * __logf(z2));

    float dotpc = pp0 * cc0 + pp1 * cc1 + pp2 * cc2;
    float np = sqrtf(pp0 * pp0 + pp1 * pp1 + pp2 * pp2);
    float nc = sqrtf(cc0 * cc0 + cc1 * cc1 + cc2 * cc2);
    float cosv = 0.1f + dotpc / fmaxf(np * nc, 1e-10f);
    float scale = sf * cosv / ent;

    o0 = fmaxf(a0 * scale, 0.001f);
    o1 = fmaxf(a1 * scale, 0.001f);
    o2 = fmaxf(a2 * scale, 0.001f);
}

__global__ void __launch_bounds__(TPB, 5)    // pin 5 CTAs/SM (caps regs at 51 = R6's count)
alpha_kernel(const float* __restrict__ prnt,
             const float* __restrict__ child,
             const float* __restrict__ Mg,
             const float* __restrict__ Bg,
             const float* __restrict__ zeps_p,
             const float* __restrict__ sf_p,
             const int*   __restrict__ rels,
             float* __restrict__ out,
             int n)
{
    __shared__ float4 sRv[64 * 3];       // only smem: 3KB rel table -> high occupancy

    const int tid = threadIdx.x;
    const int g   = blockIdx.x * TPB + tid;  // global thread id
    const int e0  = g * 4;                   // first edge of this thread

    // rel table -> shared, packed: sRv[rel*3+i] = (M[i][0..2], beta[i])
    if (tid < 64 * 3) {
        int rel = tid / 3, row = tid - rel * 3;
        float4 q;
        q.x = Mg[rel * 9 + row * 3 + 0];
        q.y = Mg[rel * 9 + row * 3 + 1];
        q.z = Mg[rel * 9 + row * 3 + 2];
        q.w = Bg[rel * 3 + row];
        sRv[tid] = q;
    }

    const bool full = (e0 + 4) <= n;

    // issue all global loads before the barrier (overlap with table setup)
    float4 pa, pb, pc, ca, cb, cc;
    int r0 = 0, r1 = 0, r2 = 0, r3 = 0;
    if (full) {
        const float4* gp = (const float4*)prnt + (size_t)g * 3;
        const float4* gc = (const float4*)child + (size_t)g * 3;
        pa = gp[0]; pb = gp[1]; pc = gp[2];
        ca = gc[0]; cb = gc[1]; cc = gc[2];
        int4 rr = ((const int4*)rels)[g];
        r0 = rr.x; r1 = rr.y; r2 = rr.z; r3 = rr.w;
    } else if (e0 < n) {
        float tmp[24];
        int cnt = n - e0;                // 1..3 edges
        #pragma unroll 1
        for (int i = 0; i < cnt * 3; i++) {
            tmp[i]      = prnt[(size_t)e0 * 3 + i];
            tmp[12 + i] = child[(size_t)e0 * 3 + i];
        }
        for (int i = cnt * 3; i < 12; i++) { tmp[i] = 0.25f; tmp[12 + i] = 0.25f; }
        pa = make_float4(tmp[0], tmp[1], tmp[2], tmp[3]);
        pb = make_float4(tmp[4], tmp[5], tmp[6], tmp[7]);
        pc = make_float4(tmp[8], tmp[9], tmp[10], tmp[11]);
        ca = make_float4(tmp[12], tmp[13], tmp[14], tmp[15]);
        cb = make_float4(tmp[16], tmp[17], tmp[18], tmp[19]);
        cc = make_float4(tmp[20], tmp[21], tmp[22], tmp[23]);
        r0 = rels[e0];
        r1 = (e0 + 1 < n) ? rels[e0 + 1] : 0;
        r2 = (e0 + 2 < n) ? rels[e0 + 2] : 0;
        r3 = (e0 + 3 < n) ? rels[e0 + 3] : 0;
    } else {
        pa = pb = pc = ca = cb = cc = make_float4(0.25f, 0.25f, 0.25f, 0.25f);
    }
    const float zeps = __ldg(zeps_p);
    const float sf   = __ldg(sf_p);

    __syncthreads();

    float4 oa, ob, oc;
    edge_compute(pa.x, pa.y, pa.z,  ca.x, ca.y, ca.z,  r0, zeps, sf, sRv, oa.x, oa.y, oa.z);
    edge_compute(pa.w, pb.x, pb.y,  ca.w, cb.x, cb.y,  r1, zeps, sf, sRv, oa.w, ob.x, ob.y);
    edge_compute(pb.z, pb.w, pc.x,  cb.z, cb.w, cc.x,  r2, zeps, sf, sRv, ob.z, ob.w, oc.x);
    edge_compute(pc.y, pc.z, pc.w,  cc.y, cc.z, cc.w,  r3, zeps, sf, sRv, oc.y, oc.z, oc.w);

    if (full) {
        float4* go = (float4*)out + (size_t)g * 3;
        go[0] = oa; go[1] = ob; go[2] = oc;
    } else if (e0 < n) {
        float res[12] = {oa.x, oa.y, oa.z, oa.w, ob.x, ob.y, ob.z, ob.w,
                         oc.x, oc.y, oc.z, oc.w};
        int cnt = n - e0;
        #pragma unroll 1
        for (int i = 0; i < cnt * 3; i++)
            out[(size_t)e0 * 3 + i] = res[i];
    }
}

extern "C" void kernel_launch(void* const* d_in, const int* in_sizes, int n_in,
                              void* d_out, int out_size) {
    // metadata order: prnt_probs, child_probs, M, beta, z_epsilon, scale_factor, rels, var_sfx
    const float* prnt  = (const float*)d_in[0];
    const float* child = (const float*)d_in[1];
    const float* Mg    = (const float*)d_in[2];
    const float* Bg    = (const float*)d_in[3];
    const float* zeps  = (const float*)d_in[4];
    const float* sf    = (const float*)d_in[5];
    const int*   rels  = (const int*)d_in[6];
    float* out = (float*)d_out;

    int n = in_sizes[6];                       // number of edges
    int blocks = (n + EPB - 1) / EPB;
    if (blocks == 0) blocks = 1;

    alpha_kernel<<<blocks, TPB>>>(prnt, child, Mg, Bg, zeps, sf, rels, out, n);
}